// round 2
// baseline (speedup 1.0000x reference)
#include <cuda_runtime.h>
#include <math.h>

// Causal self-attention, B=4, S=4096, D=64, fp32.
// Flash-attention, D split 4-way across threads:
//   thread = (row_in_tile, chunk): rowt = tid>>2 owns q row, chunk = tid&3
//   owns 16 of the 64 dims. Dot product finished with 2 shfl.xor steps
//   inside each lane-quad; softmax state kept redundantly per lane.

#define BM 32          // q rows per CTA
#define BN 64          // k rows per smem tile
#define DH 64          // head dim
#define TPR 4          // threads per row
#define CH (DH / TPR)  // 16 dims per thread
#define NCH4 (CH / 4)  // 4 float4 per thread
#define NTHREADS (BM * TPR)   // 128

__device__ __forceinline__ float ex2_approx(float x) {
    float y;
    asm("ex2.approx.f32 %0, %1;" : "=f"(y) : "f"(x));
    return y;
}

struct SoftmaxState {
    float m, l;
    float4 o4[NCH4];
};

// Process one 64-wide K/V tile. MASKED: apply causal predicate.
template <bool MASKED>
__device__ __forceinline__ void process_tile(
    const float* __restrict__ Ks, const float* __restrict__ Vs,
    const float4 (&q4)[NCH4], SoftmaxState& st,
    int chunk, int jmax_thread /* only used if MASKED */) {
#pragma unroll 4
    for (int j = 0; j < BN; j++) {
        const float4* krow = reinterpret_cast<const float4*>(Ks + j * DH + chunk * CH);
        float sx = 0.f, sy = 0.f, sz = 0.f, sw = 0.f;
#pragma unroll
        for (int i = 0; i < NCH4; i++) {
            float4 kk = krow[i];
            sx = fmaf(q4[i].x, kk.x, sx);
            sy = fmaf(q4[i].y, kk.y, sy);
            sz = fmaf(q4[i].z, kk.z, sz);
            sw = fmaf(q4[i].w, kk.w, sw);
        }
        float s = (sx + sy) + (sz + sw);
        // reduce over the 4 chunk lanes (lanes of a quad are always converged)
        s += __shfl_xor_sync(0xffffffffu, s, 1);
        s += __shfl_xor_sync(0xffffffffu, s, 2);

        if (MASKED) {
            if (j > jmax_thread) s = -1e30f;   // j==0 always valid -> m finite
        }

        float m_new = fmaxf(st.m, s);
        if (m_new > st.m) {
            float c = ex2_approx(st.m - m_new);
            st.l *= c;
#pragma unroll
            for (int i = 0; i < NCH4; i++) {
                st.o4[i].x *= c; st.o4[i].y *= c;
                st.o4[i].z *= c; st.o4[i].w *= c;
            }
            st.m = m_new;
        }
        float p = ex2_approx(s - st.m);
        st.l += p;

        const float4* vrow = reinterpret_cast<const float4*>(Vs + j * DH + chunk * CH);
#pragma unroll
        for (int i = 0; i < NCH4; i++) {
            float4 vv = vrow[i];
            st.o4[i].x = fmaf(p, vv.x, st.o4[i].x);
            st.o4[i].y = fmaf(p, vv.y, st.o4[i].y);
            st.o4[i].z = fmaf(p, vv.z, st.o4[i].z);
            st.o4[i].w = fmaf(p, vv.w, st.o4[i].w);
        }
    }
}

__global__ __launch_bounds__(NTHREADS)
void fa_causal_kernel(const float* __restrict__ Q,
                      const float* __restrict__ K,
                      const float* __restrict__ V,
                      float* __restrict__ O,
                      int B, int S) {
    __shared__ float Ks[BN * DH];
    __shared__ float Vs[BN * DH];

    const int num_qt = S / BM;                 // 128
    const int idx = blockIdx.x;
    const int b   = idx % B;
    const int qt  = num_qt - 1 - (idx / B);    // heavy q-tiles first
    const int tid = threadIdx.x;
    const int rowt  = tid >> 2;                // 0..31
    const int chunk = tid & 3;                 // 0..3
    const int r = qt * BM + rowt;              // this thread's q row

    // exactly one partial (causal-masked) tile per CTA
    const int num_full = (qt * BM) / BN;               // qt/2
    const int part_off = qt * BM - num_full * BN;      // 0 or 32
    const int jmax_thread = part_off + rowt;           // valid j <= this

    const float scale = 0.125f * 1.44269504088896340736f;  // 1/sqrt(64)*log2(e)
    const float4* qptr = reinterpret_cast<const float4*>(
        Q + ((size_t)b * S + r) * DH + chunk * CH);

    float4 q4[NCH4];
#pragma unroll
    for (int i = 0; i < NCH4; i++) {
        float4 v = qptr[i];
        v.x *= scale; v.y *= scale; v.z *= scale; v.w *= scale;
        q4[i] = v;
    }

    SoftmaxState st;
    st.m = -INFINITY;
    st.l = 0.f;
#pragma unroll
    for (int i = 0; i < NCH4; i++) st.o4[i] = make_float4(0.f, 0.f, 0.f, 0.f);

    const int num_tiles = num_full + 1;
    for (int kt = 0; kt < num_tiles; kt++) {
        // cooperative tile load: K and V, 64x64 fp32 each, coalesced float4
        const float4* kbase = reinterpret_cast<const float4*>(
            K + ((size_t)b * S + (size_t)kt * BN) * DH);
        const float4* vbase = reinterpret_cast<const float4*>(
            V + ((size_t)b * S + (size_t)kt * BN) * DH);
        float4* ks4 = reinterpret_cast<float4*>(Ks);
        float4* vs4 = reinterpret_cast<float4*>(Vs);
#pragma unroll
        for (int i = 0; i < (BN * DH / 4) / NTHREADS; i++) {   // 8 iters
            int e = i * NTHREADS + tid;
            ks4[e] = kbase[e];
            vs4[e] = vbase[e];
        }
        __syncthreads();

        if (kt < num_full)
            process_tile<false>(Ks, Vs, q4, st, chunk, 0);
        else
            process_tile<true>(Ks, Vs, q4, st, chunk, jmax_thread);

        __syncthreads();
    }

    const float inv_l = 1.f / st.l;
    float4* optr = reinterpret_cast<float4*>(
        O + ((size_t)b * S + r) * DH + chunk * CH);
#pragma unroll
    for (int i = 0; i < NCH4; i++) {
        float4 v = st.o4[i];
        v.x *= inv_l; v.y *= inv_l; v.z *= inv_l; v.w *= inv_l;
        optr[i] = v;
    }
}

extern "C" void kernel_launch(void* const* d_in, const int* in_sizes, int n_in,
                              void* d_out, int out_size) {
    const float* Q = (const float*)d_in[0];
    const float* K = (const float*)d_in[1];
    const float* V = (const float*)d_in[2];
    float* O = (float*)d_out;

    const int B = 4, S = 4096;
    const int grid = B * (S / BM);   // 512 CTAs
    fa_causal_kernel<<<grid, NTHREADS>>>(Q, K, V, O, B, S);
}

// round 3
// speedup vs baseline: 3.7777x; 3.7777x over previous
#include <cuda_runtime.h>
#include <math.h>

// Causal self-attention, B=4, S=4096, D=64, fp32.
// R3: R1 structure (1 q-row/thread, warp-uniform broadcast LDS of K/V tiles)
//     + split-K (4 splits, merged by a combine kernel)
//     + packed fp32x2 FMA (fma.rn.f32x2) for both GEMMs.

#define BM 64
#define BN 64
#define DH 64
#define NTHREADS 64
#define SPLITS 4
#define BB 4
#define SS 4096
#define NROWS (BB * SS)          // 16384
#define NP2 (DH / 2)             // 32 packed pairs per row

typedef unsigned long long ull;

// Scratch: unnormalized partial O and (m, l) per (split, row).
__device__ float g_pO[SPLITS * NROWS * DH];      // 16.8M floats
__device__ float g_ml[SPLITS * NROWS * 2];

__device__ __forceinline__ float ex2_approx(float x) {
    float y;
    asm("ex2.approx.f32 %0, %1;" : "=f"(y) : "f"(x));
    return y;
}
__device__ __forceinline__ ull pack2(float lo, float hi) {
    ull r; asm("mov.b64 %0, {%1, %2};" : "=l"(r) : "f"(lo), "f"(hi)); return r;
}
__device__ __forceinline__ void unpack2(ull v, float& lo, float& hi) {
    asm("mov.b64 {%0, %1}, %2;" : "=f"(lo), "=f"(hi) : "l"(v));
}
__device__ __forceinline__ ull fma2(ull a, ull b, ull c) {
    ull d; asm("fma.rn.f32x2 %0, %1, %2, %3;" : "=l"(d) : "l"(a), "l"(b), "l"(c)); return d;
}
__device__ __forceinline__ ull mul2(ull a, ull b) {
    ull d; asm("mul.rn.f32x2 %0, %1, %2;" : "=l"(d) : "l"(a), "l"(b)); return d;
}

__global__ __launch_bounds__(NTHREADS)
void fa_causal_split_kernel(const float* __restrict__ Q,
                            const float* __restrict__ K,
                            const float* __restrict__ V) {
    __shared__ __align__(16) float Ks[BN * DH];
    __shared__ __align__(16) float Vs[BN * DH];

    const int num_qt = SS / BM;                    // 64
    const int idx   = blockIdx.x;
    const int split = idx & (SPLITS - 1);
    const int rest  = idx >> 2;
    const int b     = rest % BB;
    const int qt    = num_qt - 1 - (rest / BB);    // heavy q-tiles first
    const int tid   = threadIdx.x;
    const int r     = qt * BM + tid;               // this thread's q row
    const int row_g = b * SS + r;

    float* po = g_pO + ((size_t)split * NROWS + row_g) * DH;
    float* pml = g_ml + ((size_t)split * NROWS + row_g) * 2;

    // split's tile range over [0, qt]
    const int len = (qt + SPLITS) / SPLITS;        // ceil((qt+1)/SPLITS)
    const int t0  = split * len;
    const int t1  = min(t0 + len, qt + 1);

    if (t0 >= t1) {   // empty split: neutral partial
#pragma unroll
        for (int i = 0; i < DH; i++) po[i] = 0.f;
        pml[0] = -INFINITY;
        pml[1] = 0.f;
        return;
    }

    // q row pre-scaled into exp2 domain: (1/sqrt(64)) * log2(e)
    const float scale = 0.125f * 1.44269504088896340736f;
    const float* qrow = Q + (size_t)row_g * DH;
    ull q2[NP2];
#pragma unroll
    for (int i = 0; i < NP2; i++)
        q2[i] = pack2(qrow[2 * i] * scale, qrow[2 * i + 1] * scale);

    ull o2[NP2];
#pragma unroll
    for (int i = 0; i < NP2; i++) o2[i] = 0ull;
    float m = -INFINITY;
    float l = 0.f;

    for (int kt = t0; kt < t1; kt++) {
        // cooperative coalesced tile load (64x64 fp32 K and V)
        const float4* kbase = reinterpret_cast<const float4*>(
            K + ((size_t)b * SS + (size_t)kt * BN) * DH);
        const float4* vbase = reinterpret_cast<const float4*>(
            V + ((size_t)b * SS + (size_t)kt * BN) * DH);
        float4* ks4 = reinterpret_cast<float4*>(Ks);
        float4* vs4 = reinterpret_cast<float4*>(Vs);
#pragma unroll
        for (int i = 0; i < (BN * DH / 4) / NTHREADS; i++) {   // 16 iters
            int e = i * NTHREADS + tid;
            ks4[e] = kbase[e];
            vs4[e] = vbase[e];
        }
        __syncthreads();

        const int jmax = (kt == qt) ? (tid + 1) : BN;   // diagonal tile mask

        for (int j = 0; j < jmax; j++) {
            const ulonglong2* krow =
                reinterpret_cast<const ulonglong2*>(Ks + j * DH);
            ull a0 = 0ull, a1 = 0ull, a2 = 0ull, a3 = 0ull;
#pragma unroll
            for (int i = 0; i < NP2 / 4; i++) {            // 8 iters, 4 pairs each
                ulonglong2 k01 = krow[2 * i];
                ulonglong2 k23 = krow[2 * i + 1];
                a0 = fma2(q2[4 * i + 0], k01.x, a0);
                a1 = fma2(q2[4 * i + 1], k01.y, a1);
                a2 = fma2(q2[4 * i + 2], k23.x, a2);
                a3 = fma2(q2[4 * i + 3], k23.y, a3);
            }
            float s;
            {
                float x0, x1, y0, y1, z0, z1, w0, w1;
                unpack2(a0, x0, x1); unpack2(a1, y0, y1);
                unpack2(a2, z0, z1); unpack2(a3, w0, w1);
                s = ((x0 + x1) + (y0 + y1)) + ((z0 + z1) + (w0 + w1));
            }

            float m_new = fmaxf(m, s);
            if (m_new > m) {                 // rare rescale
                float c = ex2_approx(m - m_new);
                ull c2 = pack2(c, c);
                l *= c;
#pragma unroll
                for (int i = 0; i < NP2; i++) o2[i] = mul2(c2, o2[i]);
                m = m_new;
            }
            float p = ex2_approx(s - m);
            l += p;
            ull p2 = pack2(p, p);

            const ulonglong2* vrow =
                reinterpret_cast<const ulonglong2*>(Vs + j * DH);
#pragma unroll
            for (int i = 0; i < NP2 / 2; i++) {            // 16 iters
                ulonglong2 vv = vrow[i];
                o2[2 * i + 0] = fma2(p2, vv.x, o2[2 * i + 0]);
                o2[2 * i + 1] = fma2(p2, vv.y, o2[2 * i + 1]);
            }
        }
        __syncthreads();
    }

    // store unnormalized partial
#pragma unroll
    for (int i = 0; i < NP2; i++) {
        float lo, hi;
        unpack2(o2[i], lo, hi);
        po[2 * i] = lo;
        po[2 * i + 1] = hi;
    }
    pml[0] = m;
    pml[1] = l;
}

// Merge the 4 split partials per row: O = sum_s e^{m_s-M} o_s / sum_s e^{m_s-M} l_s
__global__ __launch_bounds__(256)
void fa_combine_kernel(float* __restrict__ O) {
    const int gid  = blockIdx.x * 256 + threadIdx.x;   // 65536 threads
    const int part = gid & 3;                          // 16 dims each
    const int row  = gid >> 2;

    float mv[SPLITS], lv[SPLITS];
#pragma unroll
    for (int s = 0; s < SPLITS; s++) {
        mv[s] = g_ml[((size_t)s * NROWS + row) * 2 + 0];
        lv[s] = g_ml[((size_t)s * NROWS + row) * 2 + 1];
    }
    float M = fmaxf(fmaxf(mv[0], mv[1]), fmaxf(mv[2], mv[3]));
    float w[SPLITS], L = 0.f;
#pragma unroll
    for (int s = 0; s < SPLITS; s++) {
        w[s] = ex2_approx(mv[s] - M);     // -inf -> 0 for empty splits
        L += w[s] * lv[s];
    }
    const float inv = 1.f / L;

    float4 acc[4];
#pragma unroll
    for (int i = 0; i < 4; i++) acc[i] = make_float4(0.f, 0.f, 0.f, 0.f);
#pragma unroll
    for (int s = 0; s < SPLITS; s++) {
        const float4* p = reinterpret_cast<const float4*>(
            g_pO + ((size_t)s * NROWS + row) * DH + part * 16);
        float ws = w[s];
#pragma unroll
        for (int i = 0; i < 4; i++) {
            float4 v = p[i];
            acc[i].x = fmaf(ws, v.x, acc[i].x);
            acc[i].y = fmaf(ws, v.y, acc[i].y);
            acc[i].z = fmaf(ws, v.z, acc[i].z);
            acc[i].w = fmaf(ws, v.w, acc[i].w);
        }
    }
    float4* out = reinterpret_cast<float4*>(O + (size_t)row * DH + part * 16);
#pragma unroll
    for (int i = 0; i < 4; i++) {
        float4 v = acc[i];
        v.x *= inv; v.y *= inv; v.z *= inv; v.w *= inv;
        out[i] = v;
    }
}

extern "C" void kernel_launch(void* const* d_in, const int* in_sizes, int n_in,
                              void* d_out, int out_size) {
    const float* Q = (const float*)d_in[0];
    const float* K = (const float*)d_in[1];
    const float* V = (const float*)d_in[2];
    float* O = (float*)d_out;

    const int grid = BB * (SS / BM) * SPLITS;   // 1024 CTAs
    fa_causal_split_kernel<<<grid, NTHREADS>>>(Q, K, V);
    fa_combine_kernel<<<NROWS * 4 / 256, 256>>>(O);
}

// round 5
// speedup vs baseline: 4.8417x; 1.2817x over previous
#include <cuda_runtime.h>
#include <cstdint>
#include <math.h>

// Causal self-attention, B=4, S=4096, D=64, fp32.
// Tensor-core flash attention: mma.sync.m16n8k8 tf32, tf32x3 error correction
// for both QK^T and PV. CTA = 64 q rows (4 warps x 16), 64-key tiles.

#define BB 4
#define SS 4096
#define DHH 64
#define BMM 64
#define NTHREADS 128

// smem layout (floats). K/V frag arrays: [tile8][u4][132] (132 = 128 + 4 pad
// so stager scatter-stores and consumer lds.128 are both bank-conflict-free).
#define OFF_KH 0
#define OFF_KL 4224
#define OFF_VH 8448
#define OFF_VL 12672
#define OFF_P  16896            // 4 warps x 2048 (hi 1024 | lo 1024)
#define SMEM_FLOATS 25088
#define SMEM_BYTES (SMEM_FLOATS * 4)

__device__ __forceinline__ float ex2a(float x) {
    float y; asm("ex2.approx.f32 %0,%1;" : "=f"(y) : "f"(x)); return y;
}

__device__ __forceinline__ void split2(float f, float& hi, float& lo) {
    hi = __uint_as_float(__float_as_uint(f) & 0xffffe000u);  // exact tf32 head
    lo = f - hi;                                             // exact residual
}

__device__ __forceinline__ void mma_tf32(float c[4],
        float a0, float a1, float a2, float a3, float b0, float b1) {
    asm("mma.sync.aligned.m16n8k8.row.col.f32.tf32.tf32.f32 "
        "{%0,%1,%2,%3},{%4,%5,%6,%7},{%8,%9},{%0,%1,%2,%3};"
        : "+f"(c[0]), "+f"(c[1]), "+f"(c[2]), "+f"(c[3])
        : "r"(__float_as_uint(a0)), "r"(__float_as_uint(a1)),
          "r"(__float_as_uint(a2)), "r"(__float_as_uint(a3)),
          "r"(__float_as_uint(b0)), "r"(__float_as_uint(b1)));
}

// tf32x3: Ah*Bh + Al*Bh + Ah*Bl
__device__ __forceinline__ void mma3(float c[4],
        const float ah[4], const float al[4],
        float bh0, float bh1, float bl0, float bl1) {
    mma_tf32(c, ah[0], ah[1], ah[2], ah[3], bh0, bh1);
    mma_tf32(c, al[0], al[1], al[2], al[3], bh0, bh1);
    mma_tf32(c, ah[0], ah[1], ah[2], ah[3], bl0, bl1);
}

__global__ __launch_bounds__(NTHREADS, 1)
void fa_mma(const float* __restrict__ Q, const float* __restrict__ K,
            const float* __restrict__ V, float* __restrict__ O) {
    extern __shared__ float sm[];
    const int idx  = blockIdx.x;
    const int b    = idx & 3;
    const int qt   = (SS / BMM) - 1 - (idx >> 2);   // heavy q-tiles first
    const int tid  = threadIdx.x;
    const int wid  = tid >> 5;
    const int lane = tid & 31;
    const int gg   = lane >> 2;    // group id (row within m16 half)
    const int c4   = lane & 3;
    const int rowbase = qt * BMM + wid * 16;
    const int r0 = rowbase + gg;
    const int r1 = r0 + 8;

    // ---- stage Q tile raw, extract persistent a-frags (hi/lo, pre-scaled)
    {
        const float4* qg4 = (const float4*)(Q + ((size_t)b * SS + qt * BMM) * DHH);
        float4* qs4 = (float4*)sm;
#pragma unroll
        for (int i = 0; i < 8; i++) qs4[i * NTHREADS + tid] = qg4[i * NTHREADS + tid];
        __syncthreads();
    }
    const float qscale = 0.125f * 1.44269504088896f;   // 1/sqrt(64) * log2(e)
    float aQh[8][4], aQl[8][4];
    {
        const int lr0 = wid * 16 + gg, lr1 = lr0 + 8;
#pragma unroll
        for (int t = 0; t < 8; t++) {
            float v0 = sm[lr0 * 64 + 8 * t + c4]     * qscale;
            float v1 = sm[lr1 * 64 + 8 * t + c4]     * qscale;
            float v2 = sm[lr0 * 64 + 8 * t + c4 + 4] * qscale;
            float v3 = sm[lr1 * 64 + 8 * t + c4 + 4] * qscale;
            split2(v0, aQh[t][0], aQl[t][0]);
            split2(v1, aQh[t][1], aQl[t][1]);
            split2(v2, aQh[t][2], aQl[t][2]);
            split2(v3, aQh[t][3], aQl[t][3]);
        }
    }
    __syncthreads();

    float o[8][4];
#pragma unroll
    for (int nn = 0; nn < 8; nn++)
#pragma unroll
        for (int c = 0; c < 4; c++) o[nn][c] = 0.f;
    float m0 = -INFINITY, m1 = -INFINITY, l0 = 0.f, l1 = 0.f;

    for (int kt = 0; kt <= qt; kt++) {
        const bool masked = (kt == qt);

        // ---- stage K: K[n][d] -> inner offset (n&7)*16 + (d&3)*4 + ((d>>2)&3)
        const float4* kg4 = (const float4*)(K + ((size_t)b * SS + kt * 64) * DHH);
        const float4* vg4 = (const float4*)(V + ((size_t)b * SS + kt * 64) * DHH);
#pragma unroll
        for (int i = 0; i < 8; i++) {
            int e = i * NTHREADS + tid;
            float4 kv = kg4[e];
            int n = e >> 4, dbase = (e & 15) << 2;
            int base = (n >> 3) * 528 + (dbase >> 4) * 132
                     + ((n & 7) * 4) * 4 + ((dbase >> 2) & 3);
            float vals[4] = {kv.x, kv.y, kv.z, kv.w};
#pragma unroll
            for (int jj = 0; jj < 4; jj++) {
                float hi, lo; split2(vals[jj], hi, lo);
                sm[OFF_KH + base + jj * 4] = hi;
                sm[OFF_KL + base + jj * 4] = lo;
            }
        }
        // ---- stage V: V[n][d] -> inner (d&7)*16 + (n&3)*4 + ((n&7)>>2) + 2*((d>>3)&1)
#pragma unroll
        for (int i = 0; i < 8; i++) {
            int e = i * NTHREADS + tid;
            float4 vv = vg4[e];
            int n = e >> 4, dbase = (e & 15) << 2;
            int kk = n >> 3, rem = n & 7;
            int jel = (rem >> 2) + 2 * ((dbase >> 3) & 1);
            int base = kk * 528 + (dbase >> 4) * 132 + (rem & 3) * 4;  // FIX: *4
            float vals[4] = {vv.x, vv.y, vv.z, vv.w};
#pragma unroll
            for (int jj = 0; jj < 4; jj++) {
                int d = dbase + jj;
                float hi, lo; split2(vals[jj], hi, lo);
                int off = base + ((d & 7) * 4) * 4 + jel;
                sm[OFF_VH + off] = hi;
                sm[OFF_VL + off] = lo;
            }
        }
        __syncthreads();

        // ---- S = Q K^T  (8 n-tiles of keys, 8 k-tiles of dims, tf32x3)
        float s[8][4];
#pragma unroll
        for (int nn = 0; nn < 8; nn++) {
            s[nn][0] = s[nn][1] = s[nn][2] = s[nn][3] = 0.f;
#pragma unroll
            for (int u = 0; u < 4; u++) {
                float4 kh = *(const float4*)&sm[OFF_KH + nn * 528 + u * 132 + lane * 4];
                float4 kl = *(const float4*)&sm[OFF_KL + nn * 528 + u * 132 + lane * 4];
                mma3(s[nn], aQh[2 * u],     aQl[2 * u],     kh.x, kh.y, kl.x, kl.y);
                mma3(s[nn], aQh[2 * u + 1], aQl[2 * u + 1], kh.z, kh.w, kl.z, kl.w);
            }
        }

        // ---- causal mask on diagonal tile
        if (masked) {
#pragma unroll
            for (int nn = 0; nn < 8; nn++) {
                int kb = kt * 64 + nn * 8 + 2 * c4;
                if (kb     > r0) s[nn][0] = -1e30f;
                if (kb + 1 > r0) s[nn][1] = -1e30f;
                if (kb     > r1) s[nn][2] = -1e30f;
                if (kb + 1 > r1) s[nn][3] = -1e30f;
            }
        }

        // ---- online softmax (rows r0: c0,c1 / r1: c2,c3), log2 domain
        float mx0 = s[0][0], mx1 = s[0][2];
#pragma unroll
        for (int nn = 0; nn < 8; nn++) {
            mx0 = fmaxf(mx0, fmaxf(s[nn][0], s[nn][1]));
            mx1 = fmaxf(mx1, fmaxf(s[nn][2], s[nn][3]));
        }
        mx0 = fmaxf(mx0, __shfl_xor_sync(0xffffffffu, mx0, 1));
        mx0 = fmaxf(mx0, __shfl_xor_sync(0xffffffffu, mx0, 2));
        mx1 = fmaxf(mx1, __shfl_xor_sync(0xffffffffu, mx1, 1));
        mx1 = fmaxf(mx1, __shfl_xor_sync(0xffffffffu, mx1, 2));
        float nm0 = fmaxf(m0, mx0), nm1 = fmaxf(m1, mx1);
        float sc0 = ex2a(m0 - nm0), sc1 = ex2a(m1 - nm1);  // ex2(-inf)=0 first tile
        m0 = nm0; m1 = nm1;
        l0 *= sc0; l1 *= sc1;
        float sum0 = 0.f, sum1 = 0.f;
#pragma unroll
        for (int nn = 0; nn < 8; nn++) {
            s[nn][0] = ex2a(s[nn][0] - m0);
            s[nn][1] = ex2a(s[nn][1] - m0);
            s[nn][2] = ex2a(s[nn][2] - m1);
            s[nn][3] = ex2a(s[nn][3] - m1);
            sum0 += s[nn][0] + s[nn][1];
            sum1 += s[nn][2] + s[nn][3];
            o[nn][0] *= sc0; o[nn][1] *= sc0;
            o[nn][2] *= sc1; o[nn][3] *= sc1;
        }
        sum0 += __shfl_xor_sync(0xffffffffu, sum0, 1);
        sum0 += __shfl_xor_sync(0xffffffffu, sum0, 2);
        sum1 += __shfl_xor_sync(0xffffffffu, sum1, 1);
        sum1 += __shfl_xor_sync(0xffffffffu, sum1, 2);
        l0 += sum0; l1 += sum1;

        // ---- P -> per-warp smem in a-frag order, reload as a-frags
        float* wP = sm + OFF_P + wid * 2048;
#pragma unroll
        for (int nn = 0; nn < 8; nn++) {
#pragma unroll
            for (int ci = 0; ci < 4; ci++) {
                int cc   = 2 * c4 + (ci & 1);
                int slot = ((cc >= 4) ? 2 : 0) + ((ci >= 2) ? 1 : 0);
                int lamp = gg * 4 + (cc & 3);
                float hi, lo; split2(s[nn][ci], hi, lo);
                wP[nn * 128 + lamp * 4 + slot] = hi;
                wP[1024 + nn * 128 + lamp * 4 + slot] = lo;
            }
        }
        __syncwarp();

        // ---- O += P V  (k-tiles over keys, n-tiles over dims, tf32x3)
#pragma unroll
        for (int kk = 0; kk < 8; kk++) {
            float4 ph = *(const float4*)&wP[kk * 128 + lane * 4];
            float4 pl = *(const float4*)&wP[1024 + kk * 128 + lane * 4];
            float ah[4] = {ph.x, ph.y, ph.z, ph.w};
            float al[4] = {pl.x, pl.y, pl.z, pl.w};
#pragma unroll
            for (int w = 0; w < 4; w++) {
                float4 vh = *(const float4*)&sm[OFF_VH + kk * 528 + w * 132 + lane * 4];
                float4 vl = *(const float4*)&sm[OFF_VL + kk * 528 + w * 132 + lane * 4];
                mma3(o[2 * w],     ah, al, vh.x, vh.y, vl.x, vl.y);
                mma3(o[2 * w + 1], ah, al, vh.z, vh.w, vl.z, vl.w);
            }
        }
        __syncthreads();   // protect K/V smem before next staging
    }

    // ---- epilogue
    const float i0 = 1.f / l0, i1 = 1.f / l1;
    float* Og = O + (size_t)b * SS * 64;
#pragma unroll
    for (int nn = 0; nn < 8; nn++) {
        int col = nn * 8 + 2 * c4;
        *(float2*)&Og[(size_t)r0 * 64 + col] = make_float2(o[nn][0] * i0, o[nn][1] * i0);
        *(float2*)&Og[(size_t)r1 * 64 + col] = make_float2(o[nn][2] * i1, o[nn][3] * i1);
    }
}

extern "C" void kernel_launch(void* const* d_in, const int* in_sizes, int n_in,
                              void* d_out, int out_size) {
    const float* Q = (const float*)d_in[0];
    const float* K = (const float*)d_in[1];
    const float* V = (const float*)d_in[2];
    float* O = (float*)d_out;

    cudaFuncSetAttribute(fa_mma, cudaFuncAttributeMaxDynamicSharedMemorySize, SMEM_BYTES);
    fa_mma<<<BB * (SS / BMM), NTHREADS, SMEM_BYTES>>>(Q, K, V, O);
}

// round 6
// speedup vs baseline: 7.7945x; 1.6099x over previous
#include <cuda_runtime.h>
#include <cstdint>
#include <math.h>

// Causal self-attention, B=4, S=4096, D=64, fp32.
// Tensor-core flash attention (mma.sync m16n8k8 tf32, tf32x3 correction)
// + 4-way split-K with a combine pass.

#define BB 4
#define SS 4096
#define DHH 64
#define BMM 64
#define NTHREADS 128
#define SPLITS 4
#define NROWS (BB * SS)

// smem layout (floats). K/V frag arrays: [tile8][u4][132] (132 = 128 + 4 pad).
#define OFF_KH 0
#define OFF_KL 4224
#define OFF_VH 8448
#define OFF_VL 12672
#define OFF_P  16896            // 4 warps x 2048 (hi 1024 | lo 1024)
#define SMEM_FLOATS 25088
#define SMEM_BYTES (SMEM_FLOATS * 4)

// Scratch: unnormalized partial O and (m, l) per (split, row).
__device__ float g_pO[SPLITS * NROWS * DHH];
__device__ float g_ml[SPLITS * NROWS * 2];

__device__ __forceinline__ float ex2a(float x) {
    float y; asm("ex2.approx.f32 %0,%1;" : "=f"(y) : "f"(x)); return y;
}

__device__ __forceinline__ void split2(float f, float& hi, float& lo) {
    hi = __uint_as_float(__float_as_uint(f) & 0xffffe000u);
    lo = f - hi;
}

__device__ __forceinline__ void mma_tf32(float c[4],
        float a0, float a1, float a2, float a3, float b0, float b1) {
    asm("mma.sync.aligned.m16n8k8.row.col.f32.tf32.tf32.f32 "
        "{%0,%1,%2,%3},{%4,%5,%6,%7},{%8,%9},{%0,%1,%2,%3};"
        : "+f"(c[0]), "+f"(c[1]), "+f"(c[2]), "+f"(c[3])
        : "r"(__float_as_uint(a0)), "r"(__float_as_uint(a1)),
          "r"(__float_as_uint(a2)), "r"(__float_as_uint(a3)),
          "r"(__float_as_uint(b0)), "r"(__float_as_uint(b1)));
}

__device__ __forceinline__ void mma3(float c[4],
        const float ah[4], const float al[4],
        float bh0, float bh1, float bl0, float bl1) {
    mma_tf32(c, ah[0], ah[1], ah[2], ah[3], bh0, bh1);
    mma_tf32(c, al[0], al[1], al[2], al[3], bh0, bh1);
    mma_tf32(c, ah[0], ah[1], ah[2], ah[3], bl0, bl1);
}

__global__ __launch_bounds__(NTHREADS, 1)
void fa_mma_split(const float* __restrict__ Q, const float* __restrict__ K,
                  const float* __restrict__ V) {
    extern __shared__ float sm[];
    const int idx   = blockIdx.x;
    const int split = idx & (SPLITS - 1);
    const int rest  = idx >> 2;
    const int b     = rest & 3;
    const int qt    = (SS / BMM) - 1 - (rest >> 2);   // heavy q-tiles first
    const int tid   = threadIdx.x;
    const int wid   = tid >> 5;
    const int lane  = tid & 31;
    const int gg    = lane >> 2;
    const int c4    = lane & 3;
    const int rowbase = qt * BMM + wid * 16;
    const int r0 = rowbase + gg;
    const int r1 = r0 + 8;

    float* po  = g_pO + ((size_t)split * NROWS) * DHH;
    float* pml = g_ml + ((size_t)split * NROWS) * 2;
    const int rowg_cta = b * SS + qt * BMM;   // first row of this CTA

    // split's tile range over [0, qt]
    const int len = (qt + SPLITS) / SPLITS;   // ceil((qt+1)/SPLITS)
    const int t0  = split * len;
    const int t1  = min(t0 + len, qt + 1);

    if (t0 >= t1) {   // empty split: neutral partials
        for (int i = tid; i < BMM * DHH; i += NTHREADS)
            po[(size_t)(rowg_cta + (i >> 6)) * DHH + (i & 63)] = 0.f;
        if (tid < BMM) {
            pml[(size_t)(rowg_cta + tid) * 2 + 0] = -INFINITY;
            pml[(size_t)(rowg_cta + tid) * 2 + 1] = 0.f;
        }
        return;
    }

    // ---- stage Q tile raw, extract persistent a-frags (hi/lo, pre-scaled)
    {
        const float4* qg4 = (const float4*)(Q + ((size_t)b * SS + qt * BMM) * DHH);
        float4* qs4 = (float4*)sm;
#pragma unroll
        for (int i = 0; i < 8; i++) qs4[i * NTHREADS + tid] = qg4[i * NTHREADS + tid];
        __syncthreads();
    }
    const float qscale = 0.125f * 1.44269504088896f;   // 1/sqrt(64) * log2(e)
    float aQh[8][4], aQl[8][4];
    {
        const int lr0 = wid * 16 + gg, lr1 = lr0 + 8;
#pragma unroll
        for (int t = 0; t < 8; t++) {
            float v0 = sm[lr0 * 64 + 8 * t + c4]     * qscale;
            float v1 = sm[lr1 * 64 + 8 * t + c4]     * qscale;
            float v2 = sm[lr0 * 64 + 8 * t + c4 + 4] * qscale;
            float v3 = sm[lr1 * 64 + 8 * t + c4 + 4] * qscale;
            split2(v0, aQh[t][0], aQl[t][0]);
            split2(v1, aQh[t][1], aQl[t][1]);
            split2(v2, aQh[t][2], aQl[t][2]);
            split2(v3, aQh[t][3], aQl[t][3]);
        }
    }
    __syncthreads();

    float o[8][4];
#pragma unroll
    for (int nn = 0; nn < 8; nn++)
#pragma unroll
        for (int c = 0; c < 4; c++) o[nn][c] = 0.f;
    float m0 = -INFINITY, m1 = -INFINITY, l0 = 0.f, l1 = 0.f;

    for (int kt = t0; kt < t1; kt++) {
        const bool masked = (kt == qt);

        // ---- stage K
        const float4* kg4 = (const float4*)(K + ((size_t)b * SS + kt * 64) * DHH);
        const float4* vg4 = (const float4*)(V + ((size_t)b * SS + kt * 64) * DHH);
#pragma unroll
        for (int i = 0; i < 8; i++) {
            int e = i * NTHREADS + tid;
            float4 kv = kg4[e];
            int n = e >> 4, dbase = (e & 15) << 2;
            int base = (n >> 3) * 528 + (dbase >> 4) * 132
                     + ((n & 7) * 4) * 4 + ((dbase >> 2) & 3);
            float vals[4] = {kv.x, kv.y, kv.z, kv.w};
#pragma unroll
            for (int jj = 0; jj < 4; jj++) {
                float hi, lo; split2(vals[jj], hi, lo);
                sm[OFF_KH + base + jj * 4] = hi;
                sm[OFF_KL + base + jj * 4] = lo;
            }
        }
        // ---- stage V
#pragma unroll
        for (int i = 0; i < 8; i++) {
            int e = i * NTHREADS + tid;
            float4 vv = vg4[e];
            int n = e >> 4, dbase = (e & 15) << 2;
            int kk = n >> 3, rem = n & 7;
            int jel = (rem >> 2) + 2 * ((dbase >> 3) & 1);
            int base = kk * 528 + (dbase >> 4) * 132 + (rem & 3) * 4;
            float vals[4] = {vv.x, vv.y, vv.z, vv.w};
#pragma unroll
            for (int jj = 0; jj < 4; jj++) {
                int d = dbase + jj;
                float hi, lo; split2(vals[jj], hi, lo);
                int off = base + ((d & 7) * 4) * 4 + jel;
                sm[OFF_VH + off] = hi;
                sm[OFF_VL + off] = lo;
            }
        }
        __syncthreads();

        // ---- S = Q K^T
        float s[8][4];
#pragma unroll
        for (int nn = 0; nn < 8; nn++) {
            s[nn][0] = s[nn][1] = s[nn][2] = s[nn][3] = 0.f;
#pragma unroll
            for (int u = 0; u < 4; u++) {
                float4 kh = *(const float4*)&sm[OFF_KH + nn * 528 + u * 132 + lane * 4];
                float4 kl = *(const float4*)&sm[OFF_KL + nn * 528 + u * 132 + lane * 4];
                mma3(s[nn], aQh[2 * u],     aQl[2 * u],     kh.x, kh.y, kl.x, kl.y);
                mma3(s[nn], aQh[2 * u + 1], aQl[2 * u + 1], kh.z, kh.w, kl.z, kl.w);
            }
        }

        if (masked) {
#pragma unroll
            for (int nn = 0; nn < 8; nn++) {
                int kb = kt * 64 + nn * 8 + 2 * c4;
                if (kb     > r0) s[nn][0] = -1e30f;
                if (kb + 1 > r0) s[nn][1] = -1e30f;
                if (kb     > r1) s[nn][2] = -1e30f;
                if (kb + 1 > r1) s[nn][3] = -1e30f;
            }
        }

        // ---- online softmax
        float mx0 = s[0][0], mx1 = s[0][2];
#pragma unroll
        for (int nn = 0; nn < 8; nn++) {
            mx0 = fmaxf(mx0, fmaxf(s[nn][0], s[nn][1]));
            mx1 = fmaxf(mx1, fmaxf(s[nn][2], s[nn][3]));
        }
        mx0 = fmaxf(mx0, __shfl_xor_sync(0xffffffffu, mx0, 1));
        mx0 = fmaxf(mx0, __shfl_xor_sync(0xffffffffu, mx0, 2));
        mx1 = fmaxf(mx1, __shfl_xor_sync(0xffffffffu, mx1, 1));
        mx1 = fmaxf(mx1, __shfl_xor_sync(0xffffffffu, mx1, 2));
        float nm0 = fmaxf(m0, mx0), nm1 = fmaxf(m1, mx1);
        float sc0 = ex2a(m0 - nm0), sc1 = ex2a(m1 - nm1);
        m0 = nm0; m1 = nm1;
        l0 *= sc0; l1 *= sc1;
        float sum0 = 0.f, sum1 = 0.f;
#pragma unroll
        for (int nn = 0; nn < 8; nn++) {
            s[nn][0] = ex2a(s[nn][0] - m0);
            s[nn][1] = ex2a(s[nn][1] - m0);
            s[nn][2] = ex2a(s[nn][2] - m1);
            s[nn][3] = ex2a(s[nn][3] - m1);
            sum0 += s[nn][0] + s[nn][1];
            sum1 += s[nn][2] + s[nn][3];
            o[nn][0] *= sc0; o[nn][1] *= sc0;
            o[nn][2] *= sc1; o[nn][3] *= sc1;
        }
        sum0 += __shfl_xor_sync(0xffffffffu, sum0, 1);
        sum0 += __shfl_xor_sync(0xffffffffu, sum0, 2);
        sum1 += __shfl_xor_sync(0xffffffffu, sum1, 1);
        sum1 += __shfl_xor_sync(0xffffffffu, sum1, 2);
        l0 += sum0; l1 += sum1;

        // ---- P -> per-warp smem in a-frag order
        float* wP = sm + OFF_P + wid * 2048;
#pragma unroll
        for (int nn = 0; nn < 8; nn++) {
#pragma unroll
            for (int ci = 0; ci < 4; ci++) {
                int cc   = 2 * c4 + (ci & 1);
                int slot = ((cc >= 4) ? 2 : 0) + ((ci >= 2) ? 1 : 0);
                int lamp = gg * 4 + (cc & 3);
                float hi, lo; split2(s[nn][ci], hi, lo);
                wP[nn * 128 + lamp * 4 + slot] = hi;
                wP[1024 + nn * 128 + lamp * 4 + slot] = lo;
            }
        }
        __syncwarp();

        // ---- O += P V
#pragma unroll
        for (int kk = 0; kk < 8; kk++) {
            float4 ph = *(const float4*)&wP[kk * 128 + lane * 4];
            float4 pl = *(const float4*)&wP[1024 + kk * 128 + lane * 4];
            float ah[4] = {ph.x, ph.y, ph.z, ph.w};
            float al[4] = {pl.x, pl.y, pl.z, pl.w};
#pragma unroll
            for (int w = 0; w < 4; w++) {
                float4 vh = *(const float4*)&sm[OFF_VH + kk * 528 + w * 132 + lane * 4];
                float4 vl = *(const float4*)&sm[OFF_VL + kk * 528 + w * 132 + lane * 4];
                mma3(o[2 * w],     ah, al, vh.x, vh.y, vl.x, vl.y);
                mma3(o[2 * w + 1], ah, al, vh.z, vh.w, vl.z, vl.w);
            }
        }
        __syncthreads();
    }

    // ---- write partials (unnormalized O + per-row m,l)
    const int rg0 = b * SS + r0, rg1 = b * SS + r1;
#pragma unroll
    for (int nn = 0; nn < 8; nn++) {
        int col = nn * 8 + 2 * c4;
        *(float2*)&po[(size_t)rg0 * DHH + col] = make_float2(o[nn][0], o[nn][1]);
        *(float2*)&po[(size_t)rg1 * DHH + col] = make_float2(o[nn][2], o[nn][3]);
    }
    if (c4 == 0) {
        pml[(size_t)rg0 * 2 + 0] = m0;
        pml[(size_t)rg0 * 2 + 1] = l0;
        pml[(size_t)rg1 * 2 + 0] = m1;
        pml[(size_t)rg1 * 2 + 1] = l1;
    }
}

// Merge split partials: O = sum_s w_s o_s / sum_s w_s l_s, w_s = 2^(m_s - M)
__global__ __launch_bounds__(256)
void fa_combine_kernel(float* __restrict__ O) {
    const int gid  = blockIdx.x * 256 + threadIdx.x;
    const int part = gid & 3;
    const int row  = gid >> 2;

    float mv[SPLITS], lv[SPLITS];
#pragma unroll
    for (int s = 0; s < SPLITS; s++) {
        mv[s] = g_ml[((size_t)s * NROWS + row) * 2 + 0];
        lv[s] = g_ml[((size_t)s * NROWS + row) * 2 + 1];
    }
    float M = fmaxf(fmaxf(mv[0], mv[1]), fmaxf(mv[2], mv[3]));
    float w[SPLITS], L = 0.f;
#pragma unroll
    for (int s = 0; s < SPLITS; s++) {
        w[s] = ex2a(mv[s] - M);
        L += w[s] * lv[s];
    }
    const float inv = 1.f / L;

    float4 acc[4];
#pragma unroll
    for (int i = 0; i < 4; i++) acc[i] = make_float4(0.f, 0.f, 0.f, 0.f);
#pragma unroll
    for (int s = 0; s < SPLITS; s++) {
        const float4* p = (const float4*)(
            g_pO + ((size_t)s * NROWS + row) * DHH + part * 16);
        float ws = w[s];
#pragma unroll
        for (int i = 0; i < 4; i++) {
            float4 v = p[i];
            acc[i].x = fmaf(ws, v.x, acc[i].x);
            acc[i].y = fmaf(ws, v.y, acc[i].y);
            acc[i].z = fmaf(ws, v.z, acc[i].z);
            acc[i].w = fmaf(ws, v.w, acc[i].w);
        }
    }
    float4* out = (float4*)(O + (size_t)row * DHH + part * 16);
#pragma unroll
    for (int i = 0; i < 4; i++) {
        float4 v = acc[i];
        v.x *= inv; v.y *= inv; v.z *= inv; v.w *= inv;
        out[i] = v;
    }
}

extern "C" void kernel_launch(void* const* d_in, const int* in_sizes, int n_in,
                              void* d_out, int out_size) {
    const float* Q = (const float*)d_in[0];
    const float* K = (const float*)d_in[1];
    const float* V = (const float*)d_in[2];
    float* O = (float*)d_out;

    cudaFuncSetAttribute(fa_mma_split,
                         cudaFuncAttributeMaxDynamicSharedMemorySize, SMEM_BYTES);
    const int grid = SPLITS * BB * (SS / BMM);   // 1024 CTAs
    fa_mma_split<<<grid, NTHREADS, SMEM_BYTES>>>(Q, K, V);
    fa_combine_kernel<<<NROWS * 4 / 256, 256>>>(O);
}

// round 8
// speedup vs baseline: 9.9012x; 1.2703x over previous
#include <cuda_runtime.h>
#include <cstdint>
#include <math.h>

// Causal self-attention, B=4, S=4096, D=64, fp32.
// Tensor-core flash attention (mma.sync m16n8k8 tf32) + 4-way split-K.
// R8: K/V staged RAW (hi/lo derived in registers), P stored once as tf32
// (rna-rounded), PV uses 2 MMAs (P~*Vh + P~*Vl), QK^T keeps exact x3.

#define BB 4
#define SS 4096
#define DHH 64
#define BMM 64
#define NTHREADS 128
#define SPLITS 4
#define NROWS (BB * SS)

// smem (floats): raw K [8][4][132], raw V [8][4][132], P 4 warps x 1024.
#define OFF_K 0
#define OFF_V 4224
#define OFF_P 8448
#define SMEM_FLOATS 12544
#define SMEM_BYTES (SMEM_FLOATS * 4)

__device__ float g_pO[SPLITS * NROWS * DHH];
__device__ float g_ml[SPLITS * NROWS * 2];

__device__ __forceinline__ float ex2a(float x) {
    float y; asm("ex2.approx.f32 %0,%1;" : "=f"(y) : "f"(x)); return y;
}
__device__ __forceinline__ void split2(float f, float& hi, float& lo) {
    hi = __uint_as_float(__float_as_uint(f) & 0xffffe000u);  // exact head
    lo = f - hi;                                             // exact residual
}
__device__ __forceinline__ float tf32_rna(float x) {
    unsigned y;   // cvt.rna.tf32.f32 requires a .b32 destination
    asm("cvt.rna.tf32.f32 %0, %1;" : "=r"(y) : "f"(x));
    return __uint_as_float(y);
}

__device__ __forceinline__ void mma_tf32(float c[4],
        float a0, float a1, float a2, float a3, float b0, float b1) {
    asm("mma.sync.aligned.m16n8k8.row.col.f32.tf32.tf32.f32 "
        "{%0,%1,%2,%3},{%4,%5,%6,%7},{%8,%9},{%0,%1,%2,%3};"
        : "+f"(c[0]), "+f"(c[1]), "+f"(c[2]), "+f"(c[3])
        : "r"(__float_as_uint(a0)), "r"(__float_as_uint(a1)),
          "r"(__float_as_uint(a2)), "r"(__float_as_uint(a3)),
          "r"(__float_as_uint(b0)), "r"(__float_as_uint(b1)));
}
// exact-split x3 (QK^T): Ah*Bh + Al*Bh + Ah*Bl
__device__ __forceinline__ void mma3(float c[4],
        const float ah[4], const float al[4],
        float bh0, float bh1, float bl0, float bl1) {
    mma_tf32(c, ah[0], ah[1], ah[2], ah[3], bh0, bh1);
    mma_tf32(c, al[0], al[1], al[2], al[3], bh0, bh1);
    mma_tf32(c, ah[0], ah[1], ah[2], ah[3], bl0, bl1);
}
// x2 (PV): A*Bh + A*Bl, A already tf32-rounded
__device__ __forceinline__ void mma2(float c[4],
        const float a[4], float bh0, float bh1, float bl0, float bl1) {
    mma_tf32(c, a[0], a[1], a[2], a[3], bh0, bh1);
    mma_tf32(c, a[0], a[1], a[2], a[3], bl0, bl1);
}

__global__ __launch_bounds__(NTHREADS, 1)
void fa_mma_split(const float* __restrict__ Q, const float* __restrict__ K,
                  const float* __restrict__ V) {
    extern __shared__ float sm[];
    const int idx   = blockIdx.x;
    const int split = idx & (SPLITS - 1);
    const int rest  = idx >> 2;
    const int b     = rest & 3;
    const int qt    = (SS / BMM) - 1 - (rest >> 2);   // heavy q-tiles first
    const int tid   = threadIdx.x;
    const int wid   = tid >> 5;
    const int lane  = tid & 31;
    const int gg    = lane >> 2;
    const int c4    = lane & 3;
    const int rowbase = qt * BMM + wid * 16;
    const int r0 = rowbase + gg;
    const int r1 = r0 + 8;

    float* po  = g_pO + ((size_t)split * NROWS) * DHH;
    float* pml = g_ml + ((size_t)split * NROWS) * 2;
    const int rowg_cta = b * SS + qt * BMM;

    const int len = (qt + SPLITS) / SPLITS;
    const int t0  = split * len;
    const int t1  = min(t0 + len, qt + 1);

    if (t0 >= t1) {   // empty split: neutral partials
        for (int i = tid; i < BMM * DHH; i += NTHREADS)
            po[(size_t)(rowg_cta + (i >> 6)) * DHH + (i & 63)] = 0.f;
        if (tid < BMM) {
            pml[(size_t)(rowg_cta + tid) * 2 + 0] = -INFINITY;
            pml[(size_t)(rowg_cta + tid) * 2 + 1] = 0.f;
        }
        return;
    }

    // ---- stage Q tile raw, extract persistent a-frags (exact hi/lo, scaled)
    {
        const float4* qg4 = (const float4*)(Q + ((size_t)b * SS + qt * BMM) * DHH);
        float4* qs4 = (float4*)sm;
#pragma unroll
        for (int i = 0; i < 8; i++) qs4[i * NTHREADS + tid] = qg4[i * NTHREADS + tid];
        __syncthreads();
    }
    const float qscale = 0.125f * 1.44269504088896f;   // 1/sqrt(64) * log2(e)
    float aQh[8][4], aQl[8][4];
    {
        const int lr0 = wid * 16 + gg, lr1 = lr0 + 8;
#pragma unroll
        for (int t = 0; t < 8; t++) {
            float v0 = sm[lr0 * 64 + 8 * t + c4]     * qscale;
            float v1 = sm[lr1 * 64 + 8 * t + c4]     * qscale;
            float v2 = sm[lr0 * 64 + 8 * t + c4 + 4] * qscale;
            float v3 = sm[lr1 * 64 + 8 * t + c4 + 4] * qscale;
            split2(v0, aQh[t][0], aQl[t][0]);
            split2(v1, aQh[t][1], aQl[t][1]);
            split2(v2, aQh[t][2], aQl[t][2]);
            split2(v3, aQh[t][3], aQl[t][3]);
        }
    }
    __syncthreads();

    float o[8][4];
#pragma unroll
    for (int nn = 0; nn < 8; nn++)
#pragma unroll
        for (int c = 0; c < 4; c++) o[nn][c] = 0.f;
    float m0 = -INFINITY, m1 = -INFINITY, l0 = 0.f, l1 = 0.f;

    for (int kt = t0; kt < t1; kt++) {
        const bool masked = (kt == qt);

        // ---- stage K raw into frag-ordered layout
        const float4* kg4 = (const float4*)(K + ((size_t)b * SS + kt * 64) * DHH);
        const float4* vg4 = (const float4*)(V + ((size_t)b * SS + kt * 64) * DHH);
#pragma unroll
        for (int i = 0; i < 8; i++) {
            int e = i * NTHREADS + tid;
            float4 kv = kg4[e];
            int n = e >> 4, dbase = (e & 15) << 2;
            int base = (n >> 3) * 528 + (dbase >> 4) * 132
                     + ((n & 7) * 4) * 4 + ((dbase >> 2) & 3);
            sm[OFF_K + base +  0] = kv.x;
            sm[OFF_K + base +  4] = kv.y;
            sm[OFF_K + base +  8] = kv.z;
            sm[OFF_K + base + 12] = kv.w;
        }
        // ---- stage V raw
#pragma unroll
        for (int i = 0; i < 8; i++) {
            int e = i * NTHREADS + tid;
            float4 vv = vg4[e];
            int n = e >> 4, dbase = (e & 15) << 2;
            int kk = n >> 3, rem = n & 7;
            int jel = (rem >> 2) + 2 * ((dbase >> 3) & 1);
            int base = kk * 528 + (dbase >> 4) * 132 + (rem & 3) * 4;
            float vals[4] = {vv.x, vv.y, vv.z, vv.w};
#pragma unroll
            for (int jj = 0; jj < 4; jj++) {
                int d = dbase + jj;
                sm[OFF_V + base + ((d & 7) * 4) * 4 + jel] = vals[jj];
            }
        }
        __syncthreads();

        // ---- S = Q K^T (raw b-frags, split in registers, exact x3)
        float s[8][4];
#pragma unroll
        for (int nn = 0; nn < 8; nn++) {
            s[nn][0] = s[nn][1] = s[nn][2] = s[nn][3] = 0.f;
#pragma unroll
            for (int u = 0; u < 4; u++) {
                float4 kr = *(const float4*)&sm[OFF_K + nn * 528 + u * 132 + lane * 4];
                float khx, klx, khy, kly, khz, klz, khw, klw;
                split2(kr.x, khx, klx); split2(kr.y, khy, kly);
                split2(kr.z, khz, klz); split2(kr.w, khw, klw);
                mma3(s[nn], aQh[2 * u],     aQl[2 * u],     khx, khy, klx, kly);
                mma3(s[nn], aQh[2 * u + 1], aQl[2 * u + 1], khz, khw, klz, klw);
            }
        }

        if (masked) {
#pragma unroll
            for (int nn = 0; nn < 8; nn++) {
                int kb = kt * 64 + nn * 8 + 2 * c4;
                if (kb     > r0) s[nn][0] = -1e30f;
                if (kb + 1 > r0) s[nn][1] = -1e30f;
                if (kb     > r1) s[nn][2] = -1e30f;
                if (kb + 1 > r1) s[nn][3] = -1e30f;
            }
        }

        // ---- online softmax (p rounded to tf32; l summed from rounded p)
        float mx0 = s[0][0], mx1 = s[0][2];
#pragma unroll
        for (int nn = 0; nn < 8; nn++) {
            mx0 = fmaxf(mx0, fmaxf(s[nn][0], s[nn][1]));
            mx1 = fmaxf(mx1, fmaxf(s[nn][2], s[nn][3]));
        }
        mx0 = fmaxf(mx0, __shfl_xor_sync(0xffffffffu, mx0, 1));
        mx0 = fmaxf(mx0, __shfl_xor_sync(0xffffffffu, mx0, 2));
        mx1 = fmaxf(mx1, __shfl_xor_sync(0xffffffffu, mx1, 1));
        mx1 = fmaxf(mx1, __shfl_xor_sync(0xffffffffu, mx1, 2));
        float nm0 = fmaxf(m0, mx0), nm1 = fmaxf(m1, mx1);
        float sc0 = ex2a(m0 - nm0), sc1 = ex2a(m1 - nm1);
        m0 = nm0; m1 = nm1;
        l0 *= sc0; l1 *= sc1;
        float sum0 = 0.f, sum1 = 0.f;
#pragma unroll
        for (int nn = 0; nn < 8; nn++) {
            s[nn][0] = tf32_rna(ex2a(s[nn][0] - m0));
            s[nn][1] = tf32_rna(ex2a(s[nn][1] - m0));
            s[nn][2] = tf32_rna(ex2a(s[nn][2] - m1));
            s[nn][3] = tf32_rna(ex2a(s[nn][3] - m1));
            sum0 += s[nn][0] + s[nn][1];
            sum1 += s[nn][2] + s[nn][3];
            o[nn][0] *= sc0; o[nn][1] *= sc0;
            o[nn][2] *= sc1; o[nn][3] *= sc1;
        }
        sum0 += __shfl_xor_sync(0xffffffffu, sum0, 1);
        sum0 += __shfl_xor_sync(0xffffffffu, sum0, 2);
        sum1 += __shfl_xor_sync(0xffffffffu, sum1, 1);
        sum1 += __shfl_xor_sync(0xffffffffu, sum1, 2);
        l0 += sum0; l1 += sum1;

        // ---- P (tf32) -> per-warp smem in a-frag order
        float* wP = sm + OFF_P + wid * 1024;
#pragma unroll
        for (int nn = 0; nn < 8; nn++) {
#pragma unroll
            for (int ci = 0; ci < 4; ci++) {
                int cc   = 2 * c4 + (ci & 1);
                int slot = ((cc >= 4) ? 2 : 0) + ((ci >= 2) ? 1 : 0);
                int lamp = gg * 4 + (cc & 3);
                wP[nn * 128 + lamp * 4 + slot] = s[nn][ci];
            }
        }
        __syncwarp();

        // ---- O += P V  (raw V split in registers, x2)
#pragma unroll
        for (int kk = 0; kk < 8; kk++) {
            float4 pr = *(const float4*)&wP[kk * 128 + lane * 4];
            float a[4] = {pr.x, pr.y, pr.z, pr.w};
#pragma unroll
            for (int w = 0; w < 4; w++) {
                float4 vr = *(const float4*)&sm[OFF_V + kk * 528 + w * 132 + lane * 4];
                float vhx, vlx, vhy, vly, vhz, vlz, vhw, vlw;
                split2(vr.x, vhx, vlx); split2(vr.y, vhy, vly);
                split2(vr.z, vhz, vlz); split2(vr.w, vhw, vlw);
                mma2(o[2 * w],     a, vhx, vhy, vlx, vly);
                mma2(o[2 * w + 1], a, vhz, vhw, vlz, vlw);
            }
        }
        __syncthreads();
    }

    // ---- write partials
    const int rg0 = b * SS + r0, rg1 = b * SS + r1;
#pragma unroll
    for (int nn = 0; nn < 8; nn++) {
        int col = nn * 8 + 2 * c4;
        *(float2*)&po[(size_t)rg0 * DHH + col] = make_float2(o[nn][0], o[nn][1]);
        *(float2*)&po[(size_t)rg1 * DHH + col] = make_float2(o[nn][2], o[nn][3]);
    }
    if (c4 == 0) {
        pml[(size_t)rg0 * 2 + 0] = m0;
        pml[(size_t)rg0 * 2 + 1] = l0;
        pml[(size_t)rg1 * 2 + 0] = m1;
        pml[(size_t)rg1 * 2 + 1] = l1;
    }
}

__global__ __launch_bounds__(256)
void fa_combine_kernel(float* __restrict__ O) {
    const int gid  = blockIdx.x * 256 + threadIdx.x;
    const int part = gid & 3;
    const int row  = gid >> 2;

    float mv[SPLITS], lv[SPLITS];
#pragma unroll
    for (int s = 0; s < SPLITS; s++) {
        mv[s] = g_ml[((size_t)s * NROWS + row) * 2 + 0];
        lv[s] = g_ml[((size_t)s * NROWS + row) * 2 + 1];
    }
    float M = fmaxf(fmaxf(mv[0], mv[1]), fmaxf(mv[2], mv[3]));
    float w[SPLITS], L = 0.f;
#pragma unroll
    for (int s = 0; s < SPLITS; s++) {
        w[s] = ex2a(mv[s] - M);
        L += w[s] * lv[s];
    }
    const float inv = 1.f / L;

    float4 acc[4];
#pragma unroll
    for (int i = 0; i < 4; i++) acc[i] = make_float4(0.f, 0.f, 0.f, 0.f);
#pragma unroll
    for (int s = 0; s < SPLITS; s++) {
        const float4* p = (const float4*)(
            g_pO + ((size_t)s * NROWS + row) * DHH + part * 16);
        float ws = w[s];
#pragma unroll
        for (int i = 0; i < 4; i++) {
            float4 v = p[i];
            acc[i].x = fmaf(ws, v.x, acc[i].x);
            acc[i].y = fmaf(ws, v.y, acc[i].y);
            acc[i].z = fmaf(ws, v.z, acc[i].z);
            acc[i].w = fmaf(ws, v.w, acc[i].w);
        }
    }
    float4* out = (float4*)(O + (size_t)row * DHH + part * 16);
#pragma unroll
    for (int i = 0; i < 4; i++) {
        float4 v = acc[i];
        v.x *= inv; v.y *= inv; v.z *= inv; v.w *= inv;
        out[i] = v;
    }
}

extern "C" void kernel_launch(void* const* d_in, const int* in_sizes, int n_in,
                              void* d_out, int out_size) {
    const float* Q = (const float*)d_in[0];
    const float* K = (const float*)d_in[1];
    const float* V = (const float*)d_in[2];
    float* O = (float*)d_out;

    cudaFuncSetAttribute(fa_mma_split,
                         cudaFuncAttributeMaxDynamicSharedMemorySize, SMEM_BYTES);
    const int grid = SPLITS * BB * (SS / BMM);   // 1024 CTAs
    fa_mma_split<<<grid, NTHREADS, SMEM_BYTES>>>(Q, K, V);
    fa_combine_kernel<<<NROWS * 4 / 256, 256>>>(O);
}

// round 9
// speedup vs baseline: 11.3075x; 1.1420x over previous
#include <cuda_runtime.h>
#include <cstdint>
#include <math.h>

// Causal self-attention, B=4, S=4096, D=64, fp32.
// Tensor-core flash attention (mma.sync m16n8k8 tf32) + 4-way split-K.
// R9: Q in smem frag table (regs down), V staged pre-rounded tf32 (PV = 1 MMA),
// P reuses the K smem region after QK completes.

#define BB 4
#define SS 4096
#define DHH 64
#define BMM 64
#define NTHREADS 128
#define SPLITS 4
#define NROWS (BB * SS)

// smem (floats): K raw [8][4][132] (P overlays this during PV),
//                V tf32 [8][4][132], Q frags 4 warps x 1024.
#define OFF_K 0
#define OFF_V 4224
#define OFF_QF 8448
#define SMEM_FLOATS 12544
#define SMEM_BYTES (SMEM_FLOATS * 4)

__device__ float g_pO[SPLITS * NROWS * DHH];
__device__ float g_ml[SPLITS * NROWS * 2];

__device__ __forceinline__ float ex2a(float x) {
    float y; asm("ex2.approx.f32 %0,%1;" : "=f"(y) : "f"(x)); return y;
}
__device__ __forceinline__ void split2(float f, float& hi, float& lo) {
    hi = __uint_as_float(__float_as_uint(f) & 0xffffe000u);
    lo = f - hi;
}
__device__ __forceinline__ float tf32_rna(float x) {
    unsigned y;
    asm("cvt.rna.tf32.f32 %0, %1;" : "=r"(y) : "f"(x));
    return __uint_as_float(y);
}

__device__ __forceinline__ void mma_tf32(float c[4],
        float a0, float a1, float a2, float a3, float b0, float b1) {
    asm("mma.sync.aligned.m16n8k8.row.col.f32.tf32.tf32.f32 "
        "{%0,%1,%2,%3},{%4,%5,%6,%7},{%8,%9},{%0,%1,%2,%3};"
        : "+f"(c[0]), "+f"(c[1]), "+f"(c[2]), "+f"(c[3])
        : "r"(__float_as_uint(a0)), "r"(__float_as_uint(a1)),
          "r"(__float_as_uint(a2)), "r"(__float_as_uint(a3)),
          "r"(__float_as_uint(b0)), "r"(__float_as_uint(b1)));
}
// exact-split x3 (QK^T): Ah*Bh + Al*Bh + Ah*Bl
__device__ __forceinline__ void mma3(float c[4],
        const float ah[4], const float al[4],
        float bh0, float bh1, float bl0, float bl1) {
    mma_tf32(c, ah[0], ah[1], ah[2], ah[3], bh0, bh1);
    mma_tf32(c, al[0], al[1], al[2], al[3], bh0, bh1);
    mma_tf32(c, ah[0], ah[1], ah[2], ah[3], bl0, bl1);
}

__global__ __launch_bounds__(NTHREADS, 3)
void fa_mma_split(const float* __restrict__ Q, const float* __restrict__ K,
                  const float* __restrict__ V) {
    extern __shared__ float sm[];
    const int idx   = blockIdx.x;
    const int split = idx & (SPLITS - 1);
    const int rest  = idx >> 2;
    const int b     = rest & 3;
    const int qt    = (SS / BMM) - 1 - (rest >> 2);   // heavy q-tiles first
    const int tid   = threadIdx.x;
    const int wid   = tid >> 5;
    const int lane  = tid & 31;
    const int gg    = lane >> 2;
    const int c4    = lane & 3;
    const int rowbase = qt * BMM + wid * 16;
    const int r0 = rowbase + gg;
    const int r1 = r0 + 8;

    float* po  = g_pO + ((size_t)split * NROWS) * DHH;
    float* pml = g_ml + ((size_t)split * NROWS) * 2;
    const int rowg_cta = b * SS + qt * BMM;

    const int len = (qt + SPLITS) / SPLITS;
    const int t0  = split * len;
    const int t1  = min(t0 + len, qt + 1);

    if (t0 >= t1) {   // empty split: neutral partials
        for (int i = tid; i < BMM * DHH; i += NTHREADS)
            po[(size_t)(rowg_cta + (i >> 6)) * DHH + (i & 63)] = 0.f;
        if (tid < BMM) {
            pml[(size_t)(rowg_cta + tid) * 2 + 0] = -INFINITY;
            pml[(size_t)(rowg_cta + tid) * 2 + 1] = 0.f;
        }
        return;
    }

    // ---- stage Q tile raw (into K region), build per-warp Q frag table
    {
        const float4* qg4 = (const float4*)(Q + ((size_t)b * SS + qt * BMM) * DHH);
        float4* qs4 = (float4*)sm;
#pragma unroll
        for (int i = 0; i < 8; i++) qs4[i * NTHREADS + tid] = qg4[i * NTHREADS + tid];
        __syncthreads();
        const float qscale = 0.125f * 1.44269504088896f;  // 1/sqrt(64)*log2(e)
        const int lr0 = wid * 16 + gg, lr1 = lr0 + 8;
        float* qf = sm + OFF_QF + wid * 1024;
#pragma unroll
        for (int t = 0; t < 8; t++) {
            float v0 = sm[lr0 * 64 + 8 * t + c4]     * qscale;
            float v1 = sm[lr1 * 64 + 8 * t + c4]     * qscale;
            float v2 = sm[lr0 * 64 + 8 * t + c4 + 4] * qscale;
            float v3 = sm[lr1 * 64 + 8 * t + c4 + 4] * qscale;
            *(float4*)&qf[t * 128 + lane * 4] = make_float4(v0, v1, v2, v3);
        }
        __syncthreads();   // raw Q may now be overwritten by K staging
    }

    float o[8][4];
#pragma unroll
    for (int nn = 0; nn < 8; nn++)
#pragma unroll
        for (int c = 0; c < 4; c++) o[nn][c] = 0.f;
    float m0 = -INFINITY, m1 = -INFINITY, l0 = 0.f, l1 = 0.f;

    for (int kt = t0; kt < t1; kt++) {
        const bool masked = (kt == qt);

        // ---- stage K raw into frag-ordered layout
        const float4* kg4 = (const float4*)(K + ((size_t)b * SS + kt * 64) * DHH);
        const float4* vg4 = (const float4*)(V + ((size_t)b * SS + kt * 64) * DHH);
#pragma unroll
        for (int i = 0; i < 8; i++) {
            int e = i * NTHREADS + tid;
            float4 kv = kg4[e];
            int n = e >> 4, dbase = (e & 15) << 2;
            int base = (n >> 3) * 528 + (dbase >> 4) * 132
                     + ((n & 7) * 4) * 4 + ((dbase >> 2) & 3);
            sm[OFF_K + base +  0] = kv.x;
            sm[OFF_K + base +  4] = kv.y;
            sm[OFF_K + base +  8] = kv.z;
            sm[OFF_K + base + 12] = kv.w;
        }
        // ---- stage V pre-rounded to tf32
#pragma unroll
        for (int i = 0; i < 8; i++) {
            int e = i * NTHREADS + tid;
            float4 vv = vg4[e];
            int n = e >> 4, dbase = (e & 15) << 2;
            int kk = n >> 3, rem = n & 7;
            int jel = (rem >> 2) + 2 * ((dbase >> 3) & 1);
            int base = kk * 528 + (dbase >> 4) * 132 + (rem & 3) * 4;
            float vals[4] = {vv.x, vv.y, vv.z, vv.w};
#pragma unroll
            for (int jj = 0; jj < 4; jj++) {
                int d = dbase + jj;
                sm[OFF_V + base + ((d & 7) * 4) * 4 + jel] = tf32_rna(vals[jj]);
            }
        }
        __syncthreads();

        // ---- S = Q K^T (u outer so Q is loaded/split once per u)
        float s[8][4];
#pragma unroll
        for (int nn = 0; nn < 8; nn++)
            s[nn][0] = s[nn][1] = s[nn][2] = s[nn][3] = 0.f;
        const float* qf = sm + OFF_QF + wid * 1024;
#pragma unroll
        for (int u = 0; u < 4; u++) {
            float4 q0 = *(const float4*)&qf[(2 * u)     * 128 + lane * 4];
            float4 q1 = *(const float4*)&qf[(2 * u + 1) * 128 + lane * 4];
            float q0h[4], q0l[4], q1h[4], q1l[4];
            split2(q0.x, q0h[0], q0l[0]); split2(q0.y, q0h[1], q0l[1]);
            split2(q0.z, q0h[2], q0l[2]); split2(q0.w, q0h[3], q0l[3]);
            split2(q1.x, q1h[0], q1l[0]); split2(q1.y, q1h[1], q1l[1]);
            split2(q1.z, q1h[2], q1l[2]); split2(q1.w, q1h[3], q1l[3]);
#pragma unroll
            for (int nn = 0; nn < 8; nn++) {
                float4 kr = *(const float4*)&sm[OFF_K + nn * 528 + u * 132 + lane * 4];
                float khx, klx, khy, kly, khz, klz, khw, klw;
                split2(kr.x, khx, klx); split2(kr.y, khy, kly);
                split2(kr.z, khz, klz); split2(kr.w, khw, klw);
                mma3(s[nn], q0h, q0l, khx, khy, klx, kly);
                mma3(s[nn], q1h, q1l, khz, khw, klz, klw);
            }
        }
        __syncthreads();   // all K reads done; P may overlay the K region

        if (masked) {
#pragma unroll
            for (int nn = 0; nn < 8; nn++) {
                int kb = kt * 64 + nn * 8 + 2 * c4;
                if (kb     > r0) s[nn][0] = -1e30f;
                if (kb + 1 > r0) s[nn][1] = -1e30f;
                if (kb     > r1) s[nn][2] = -1e30f;
                if (kb + 1 > r1) s[nn][3] = -1e30f;
            }
        }

        // ---- online softmax (p rounded to tf32; l summed from rounded p)
        float mx0 = s[0][0], mx1 = s[0][2];
#pragma unroll
        for (int nn = 0; nn < 8; nn++) {
            mx0 = fmaxf(mx0, fmaxf(s[nn][0], s[nn][1]));
            mx1 = fmaxf(mx1, fmaxf(s[nn][2], s[nn][3]));
        }
        mx0 = fmaxf(mx0, __shfl_xor_sync(0xffffffffu, mx0, 1));
        mx0 = fmaxf(mx0, __shfl_xor_sync(0xffffffffu, mx0, 2));
        mx1 = fmaxf(mx1, __shfl_xor_sync(0xffffffffu, mx1, 1));
        mx1 = fmaxf(mx1, __shfl_xor_sync(0xffffffffu, mx1, 2));
        float nm0 = fmaxf(m0, mx0), nm1 = fmaxf(m1, mx1);
        float sc0 = ex2a(m0 - nm0), sc1 = ex2a(m1 - nm1);
        m0 = nm0; m1 = nm1;
        l0 *= sc0; l1 *= sc1;
        float sum0 = 0.f, sum1 = 0.f;
#pragma unroll
        for (int nn = 0; nn < 8; nn++) {
            s[nn][0] = tf32_rna(ex2a(s[nn][0] - m0));
            s[nn][1] = tf32_rna(ex2a(s[nn][1] - m0));
            s[nn][2] = tf32_rna(ex2a(s[nn][2] - m1));
            s[nn][3] = tf32_rna(ex2a(s[nn][3] - m1));
            sum0 += s[nn][0] + s[nn][1];
            sum1 += s[nn][2] + s[nn][3];
            o[nn][0] *= sc0; o[nn][1] *= sc0;
            o[nn][2] *= sc1; o[nn][3] *= sc1;
        }
        sum0 += __shfl_xor_sync(0xffffffffu, sum0, 1);
        sum0 += __shfl_xor_sync(0xffffffffu, sum0, 2);
        sum1 += __shfl_xor_sync(0xffffffffu, sum1, 1);
        sum1 += __shfl_xor_sync(0xffffffffu, sum1, 2);
        l0 += sum0; l1 += sum1;

        // ---- P (tf32) -> per-warp region overlaying K smem, a-frag order
        float* wP = sm + OFF_K + wid * 1024;
#pragma unroll
        for (int nn = 0; nn < 8; nn++) {
#pragma unroll
            for (int ci = 0; ci < 4; ci++) {
                int cc   = 2 * c4 + (ci & 1);
                int slot = ((cc >= 4) ? 2 : 0) + ((ci >= 2) ? 1 : 0);
                int lamp = gg * 4 + (cc & 3);
                wP[nn * 128 + lamp * 4 + slot] = s[nn][ci];
            }
        }
        __syncwarp();

        // ---- O += P V (both tf32, single MMA per step)
#pragma unroll
        for (int kk = 0; kk < 8; kk++) {
            float4 pr = *(const float4*)&wP[kk * 128 + lane * 4];
#pragma unroll
            for (int w = 0; w < 4; w++) {
                float4 vr = *(const float4*)&sm[OFF_V + kk * 528 + w * 132 + lane * 4];
                mma_tf32(o[2 * w],     pr.x, pr.y, pr.z, pr.w, vr.x, vr.y);
                mma_tf32(o[2 * w + 1], pr.x, pr.y, pr.z, pr.w, vr.z, vr.w);
            }
        }
        __syncthreads();
    }

    // ---- write partials
    const int rg0 = b * SS + r0, rg1 = b * SS + r1;
#pragma unroll
    for (int nn = 0; nn < 8; nn++) {
        int col = nn * 8 + 2 * c4;
        *(float2*)&po[(size_t)rg0 * DHH + col] = make_float2(o[nn][0], o[nn][1]);
        *(float2*)&po[(size_t)rg1 * DHH + col] = make_float2(o[nn][2], o[nn][3]);
    }
    if (c4 == 0) {
        pml[(size_t)rg0 * 2 + 0] = m0;
        pml[(size_t)rg0 * 2 + 1] = l0;
        pml[(size_t)rg1 * 2 + 0] = m1;
        pml[(size_t)rg1 * 2 + 1] = l1;
    }
}

__global__ __launch_bounds__(256)
void fa_combine_kernel(float* __restrict__ O) {
    const int gid  = blockIdx.x * 256 + threadIdx.x;
    const int part = gid & 3;
    const int row  = gid >> 2;

    float mv[SPLITS], lv[SPLITS];
#pragma unroll
    for (int s = 0; s < SPLITS; s++) {
        mv[s] = g_ml[((size_t)s * NROWS + row) * 2 + 0];
        lv[s] = g_ml[((size_t)s * NROWS + row) * 2 + 1];
    }
    float M = fmaxf(fmaxf(mv[0], mv[1]), fmaxf(mv[2], mv[3]));
    float w[SPLITS], L = 0.f;
#pragma unroll
    for (int s = 0; s < SPLITS; s++) {
        w[s] = ex2a(mv[s] - M);
        L += w[s] * lv[s];
    }
    const float inv = 1.f / L;

    float4 acc[4];
#pragma unroll
    for (int i = 0; i < 4; i++) acc[i] = make_float4(0.f, 0.f, 0.f, 0.f);
#pragma unroll
    for (int s = 0; s < SPLITS; s++) {
        const float4* p = (const float4*)(
            g_pO + ((size_t)s * NROWS + row) * DHH + part * 16);
        float ws = w[s];
#pragma unroll
        for (int i = 0; i < 4; i++) {
            float4 v = p[i];
            acc[i].x = fmaf(ws, v.x, acc[i].x);
            acc[i].y = fmaf(ws, v.y, acc[i].y);
            acc[i].z = fmaf(ws, v.z, acc[i].z);
            acc[i].w = fmaf(ws, v.w, acc[i].w);
        }
    }
    float4* out = (float4*)(O + (size_t)row * DHH + part * 16);
#pragma unroll
    for (int i = 0; i < 4; i++) {
        float4 v = acc[i];
        v.x *= inv; v.y *= inv; v.z *= inv; v.w *= inv;
        out[i] = v;
    }
}

extern "C" void kernel_launch(void* const* d_in, const int* in_sizes, int n_in,
                              void* d_out, int out_size) {
    const float* Q = (const float*)d_in[0];
    const float* K = (const float*)d_in[1];
    const float* V = (const float*)d_in[2];
    float* O = (float*)d_out;

    cudaFuncSetAttribute(fa_mma_split,
                         cudaFuncAttributeMaxDynamicSharedMemorySize, SMEM_BYTES);
    const int grid = SPLITS * BB * (SS / BMM);   // 1024 CTAs
    fa_mma_split<<<grid, NTHREADS, SMEM_BYTES>>>(Q, K, V);
    fa_combine_kernel<<<NROWS * 4 / 256, 256>>>(O);
}

// round 10
// speedup vs baseline: 11.7377x; 1.0380x over previous
#include <cuda_runtime.h>
#include <cstdint>
#include <math.h>

// Causal self-attention, B=4, S=4096, D=64, fp32.
// Tensor-core flash attention (mma.sync m16n8k8 tf32) + 4-way split-K.
// R10: BMM=128 (4 warps x 32 rows, two m16 groups per warp) so each K/V
// b-fragment load is amortized over 2x rows. PV in two key-halves through
// the K-region P overlay. V pre-rounded tf32 (PV = 1 MMA), QK exact x3.

#define BB 4
#define SS 4096
#define DHH 64
#define BMM 128
#define NTHREADS 128
#define SPLITS 4
#define NROWS (BB * SS)

// smem (floats): K raw [8][4][132] = 4224 (P overlays per-warp 1056 slots),
// V tf32 [8][4][132] = 4224, Q frag table 4 warps x 2048 = 8192.
#define OFF_K 0
#define OFF_V 4224
#define OFF_QF 8448
#define SMEM_FLOATS 16640
#define SMEM_BYTES (SMEM_FLOATS * 4)

__device__ float g_pO[SPLITS * NROWS * DHH];
__device__ float g_ml[SPLITS * NROWS * 2];

__device__ __forceinline__ float ex2a(float x) {
    float y; asm("ex2.approx.f32 %0,%1;" : "=f"(y) : "f"(x)); return y;
}
__device__ __forceinline__ void split2(float f, float& hi, float& lo) {
    hi = __uint_as_float(__float_as_uint(f) & 0xffffe000u);
    lo = f - hi;
}
__device__ __forceinline__ float tf32_rna(float x) {
    unsigned y;
    asm("cvt.rna.tf32.f32 %0, %1;" : "=r"(y) : "f"(x));
    return __uint_as_float(y);
}

__device__ __forceinline__ void mma_tf32(float c[4],
        float a0, float a1, float a2, float a3, float b0, float b1) {
    asm("mma.sync.aligned.m16n8k8.row.col.f32.tf32.tf32.f32 "
        "{%0,%1,%2,%3},{%4,%5,%6,%7},{%8,%9},{%0,%1,%2,%3};"
        : "+f"(c[0]), "+f"(c[1]), "+f"(c[2]), "+f"(c[3])
        : "r"(__float_as_uint(a0)), "r"(__float_as_uint(a1)),
          "r"(__float_as_uint(a2)), "r"(__float_as_uint(a3)),
          "r"(__float_as_uint(b0)), "r"(__float_as_uint(b1)));
}
__device__ __forceinline__ void mma3(float c[4],
        const float ah[4], const float al[4],
        float bh0, float bh1, float bl0, float bl1) {
    mma_tf32(c, ah[0], ah[1], ah[2], ah[3], bh0, bh1);
    mma_tf32(c, al[0], al[1], al[2], al[3], bh0, bh1);
    mma_tf32(c, ah[0], ah[1], ah[2], ah[3], bl0, bl1);
}
__device__ __forceinline__ void split4(const float4& v, float h[4], float l[4]) {
    split2(v.x, h[0], l[0]); split2(v.y, h[1], l[1]);
    split2(v.z, h[2], l[2]); split2(v.w, h[3], l[3]);
}

__global__ __launch_bounds__(NTHREADS, 2)
void fa_mma_split(const float* __restrict__ Q, const float* __restrict__ K,
                  const float* __restrict__ V) {
    extern __shared__ float sm[];
    const int idx   = blockIdx.x;
    const int split = idx & (SPLITS - 1);
    const int rest  = idx >> 2;
    const int b     = rest & 3;
    const int qt    = (SS / BMM) - 1 - (rest >> 2);   // heavy q-tiles first
    const int tid   = threadIdx.x;
    const int wid   = tid >> 5;
    const int lane  = tid & 31;
    const int gg    = lane >> 2;
    const int c4    = lane & 3;
    // 4 row groups per warp: A0, A1 (+8), B0 (+16), B1 (+24)
    const int rA0 = qt * BMM + wid * 32 + gg;
    const int rA1 = rA0 + 8;
    const int rB0 = rA0 + 16;
    const int rB1 = rA0 + 24;

    float* po  = g_pO + ((size_t)split * NROWS) * DHH;
    float* pml = g_ml + ((size_t)split * NROWS) * 2;
    const int rowg_cta = b * SS + qt * BMM;

    const int ntile = 2 * qt + 2;                 // key tiles needed
    const int len = (ntile + SPLITS - 1) / SPLITS;
    const int t0  = split * len;
    const int t1  = min(t0 + len, ntile);

    if (t0 >= t1) {   // empty split: neutral partials
        for (int i = tid; i < BMM * DHH; i += NTHREADS)
            po[(size_t)(rowg_cta + (i >> 6)) * DHH + (i & 63)] = 0.f;
        pml[(size_t)(rowg_cta + tid) * 2 + 0] = -INFINITY;
        pml[(size_t)(rowg_cta + tid) * 2 + 1] = 0.f;
        return;
    }

    // ---- stage Q tile raw (over K+V regions), build per-warp Q frag table
    {
        const float4* qg4 = (const float4*)(Q + ((size_t)b * SS + qt * BMM) * DHH);
        float4* qs4 = (float4*)sm;
#pragma unroll
        for (int i = 0; i < 16; i++) qs4[i * NTHREADS + tid] = qg4[i * NTHREADS + tid];
        __syncthreads();
        const float qscale = 0.125f * 1.44269504088896f;  // 1/sqrt(64)*log2(e)
        const int lA = wid * 32 + gg, lB = lA + 16;
        float* qf = sm + OFF_QF + wid * 2048;
#pragma unroll
        for (int t = 0; t < 8; t++) {
            float4 a, bq;
            a.x  = sm[lA * 64 + 8 * t + c4]            * qscale;
            a.y  = sm[(lA + 8) * 64 + 8 * t + c4]      * qscale;
            a.z  = sm[lA * 64 + 8 * t + c4 + 4]        * qscale;
            a.w  = sm[(lA + 8) * 64 + 8 * t + c4 + 4]  * qscale;
            bq.x = sm[lB * 64 + 8 * t + c4]            * qscale;
            bq.y = sm[(lB + 8) * 64 + 8 * t + c4]      * qscale;
            bq.z = sm[lB * 64 + 8 * t + c4 + 4]        * qscale;
            bq.w = sm[(lB + 8) * 64 + 8 * t + c4 + 4]  * qscale;
            *(float4*)&qf[t * 256 + lane * 4]       = a;
            *(float4*)&qf[t * 256 + 128 + lane * 4] = bq;
        }
        __syncthreads();   // raw Q may now be overwritten by K/V staging
    }

    float oA[8][4], oB[8][4];
#pragma unroll
    for (int nn = 0; nn < 8; nn++)
#pragma unroll
        for (int c = 0; c < 4; c++) { oA[nn][c] = 0.f; oB[nn][c] = 0.f; }
    float mA0 = -INFINITY, mA1 = -INFINITY, mB0 = -INFINITY, mB1 = -INFINITY;
    float lA0 = 0.f, lA1 = 0.f, lB0 = 0.f, lB1 = 0.f;

    for (int kt = t0; kt < t1; kt++) {
        const bool masked = (kt >= 2 * qt);

        // ---- stage K raw into frag-ordered layout
        const float4* kg4 = (const float4*)(K + ((size_t)b * SS + kt * 64) * DHH);
        const float4* vg4 = (const float4*)(V + ((size_t)b * SS + kt * 64) * DHH);
#pragma unroll
        for (int i = 0; i < 8; i++) {
            int e = i * NTHREADS + tid;
            float4 kv = kg4[e];
            int n = e >> 4, dbase = (e & 15) << 2;
            int base = (n >> 3) * 528 + (dbase >> 4) * 132
                     + ((n & 7) * 4) * 4 + ((dbase >> 2) & 3);
            sm[OFF_K + base +  0] = kv.x;
            sm[OFF_K + base +  4] = kv.y;
            sm[OFF_K + base +  8] = kv.z;
            sm[OFF_K + base + 12] = kv.w;
        }
        // ---- stage V pre-rounded to tf32
#pragma unroll
        for (int i = 0; i < 8; i++) {
            int e = i * NTHREADS + tid;
            float4 vv = vg4[e];
            int n = e >> 4, dbase = (e & 15) << 2;
            int kk = n >> 3, rem = n & 7;
            int jel = (rem >> 2) + 2 * ((dbase >> 3) & 1);
            int base = kk * 528 + (dbase >> 4) * 132 + (rem & 3) * 4;
            float vals[4] = {vv.x, vv.y, vv.z, vv.w};
#pragma unroll
            for (int jj = 0; jj < 4; jj++) {
                int d = dbase + jj;
                sm[OFF_V + base + ((d & 7) * 4) * 4 + jel] = tf32_rna(vals[jj]);
            }
        }
        __syncthreads();

        // ---- S = Q K^T (u outer; K frag shared by both row groups)
        float sA[8][4], sB[8][4];
#pragma unroll
        for (int nn = 0; nn < 8; nn++)
#pragma unroll
            for (int c = 0; c < 4; c++) { sA[nn][c] = 0.f; sB[nn][c] = 0.f; }
        const float* qf = sm + OFF_QF + wid * 2048;
#pragma unroll
        for (int u = 0; u < 4; u++) {
            float4 q0A = *(const float4*)&qf[(2 * u) * 256 + lane * 4];
            float4 q0B = *(const float4*)&qf[(2 * u) * 256 + 128 + lane * 4];
            float4 q1A = *(const float4*)&qf[(2 * u + 1) * 256 + lane * 4];
            float4 q1B = *(const float4*)&qf[(2 * u + 1) * 256 + 128 + lane * 4];
            float q0Ah[4], q0Al[4], q0Bh[4], q0Bl[4];
            float q1Ah[4], q1Al[4], q1Bh[4], q1Bl[4];
            split4(q0A, q0Ah, q0Al); split4(q0B, q0Bh, q0Bl);
            split4(q1A, q1Ah, q1Al); split4(q1B, q1Bh, q1Bl);
#pragma unroll
            for (int nn = 0; nn < 8; nn++) {
                float4 kr = *(const float4*)&sm[OFF_K + nn * 528 + u * 132 + lane * 4];
                float kh[4], kl[4];
                split4(kr, kh, kl);
                mma3(sA[nn], q0Ah, q0Al, kh[0], kh[1], kl[0], kl[1]);
                mma3(sA[nn], q1Ah, q1Al, kh[2], kh[3], kl[2], kl[3]);
                mma3(sB[nn], q0Bh, q0Bl, kh[0], kh[1], kl[0], kl[1]);
                mma3(sB[nn], q1Bh, q1Bl, kh[2], kh[3], kl[2], kl[3]);
            }
        }
        __syncthreads();   // all K reads done; P may overlay the K region

        if (masked) {
#pragma unroll
            for (int nn = 0; nn < 8; nn++) {
                int kb = kt * 64 + nn * 8 + 2 * c4;
                if (kb     > rA0) sA[nn][0] = -1e30f;
                if (kb + 1 > rA0) sA[nn][1] = -1e30f;
                if (kb     > rA1) sA[nn][2] = -1e30f;
                if (kb + 1 > rA1) sA[nn][3] = -1e30f;
                if (kb     > rB0) sB[nn][0] = -1e30f;
                if (kb + 1 > rB0) sB[nn][1] = -1e30f;
                if (kb     > rB1) sB[nn][2] = -1e30f;
                if (kb + 1 > rB1) sB[nn][3] = -1e30f;
            }
        }

        // ---- online softmax for 4 row groups
        float x0 = sA[0][0], x1 = sA[0][2], x2 = sB[0][0], x3 = sB[0][2];
#pragma unroll
        for (int nn = 0; nn < 8; nn++) {
            x0 = fmaxf(x0, fmaxf(sA[nn][0], sA[nn][1]));
            x1 = fmaxf(x1, fmaxf(sA[nn][2], sA[nn][3]));
            x2 = fmaxf(x2, fmaxf(sB[nn][0], sB[nn][1]));
            x3 = fmaxf(x3, fmaxf(sB[nn][2], sB[nn][3]));
        }
        x0 = fmaxf(x0, __shfl_xor_sync(0xffffffffu, x0, 1));
        x0 = fmaxf(x0, __shfl_xor_sync(0xffffffffu, x0, 2));
        x1 = fmaxf(x1, __shfl_xor_sync(0xffffffffu, x1, 1));
        x1 = fmaxf(x1, __shfl_xor_sync(0xffffffffu, x1, 2));
        x2 = fmaxf(x2, __shfl_xor_sync(0xffffffffu, x2, 1));
        x2 = fmaxf(x2, __shfl_xor_sync(0xffffffffu, x2, 2));
        x3 = fmaxf(x3, __shfl_xor_sync(0xffffffffu, x3, 1));
        x3 = fmaxf(x3, __shfl_xor_sync(0xffffffffu, x3, 2));
        float nA0 = fmaxf(mA0, x0), nA1 = fmaxf(mA1, x1);
        float nB0 = fmaxf(mB0, x2), nB1 = fmaxf(mB1, x3);
        float cA0 = ex2a(mA0 - nA0), cA1 = ex2a(mA1 - nA1);
        float cB0 = ex2a(mB0 - nB0), cB1 = ex2a(mB1 - nB1);
        mA0 = nA0; mA1 = nA1; mB0 = nB0; mB1 = nB1;
        lA0 *= cA0; lA1 *= cA1; lB0 *= cB0; lB1 *= cB1;
        float uA0 = 0.f, uA1 = 0.f, uB0 = 0.f, uB1 = 0.f;
#pragma unroll
        for (int nn = 0; nn < 8; nn++) {
            sA[nn][0] = tf32_rna(ex2a(sA[nn][0] - mA0));
            sA[nn][1] = tf32_rna(ex2a(sA[nn][1] - mA0));
            sA[nn][2] = tf32_rna(ex2a(sA[nn][2] - mA1));
            sA[nn][3] = tf32_rna(ex2a(sA[nn][3] - mA1));
            sB[nn][0] = tf32_rna(ex2a(sB[nn][0] - mB0));
            sB[nn][1] = tf32_rna(ex2a(sB[nn][1] - mB0));
            sB[nn][2] = tf32_rna(ex2a(sB[nn][2] - mB1));
            sB[nn][3] = tf32_rna(ex2a(sB[nn][3] - mB1));
            uA0 += sA[nn][0] + sA[nn][1];
            uA1 += sA[nn][2] + sA[nn][3];
            uB0 += sB[nn][0] + sB[nn][1];
            uB1 += sB[nn][2] + sB[nn][3];
            oA[nn][0] *= cA0; oA[nn][1] *= cA0;
            oA[nn][2] *= cA1; oA[nn][3] *= cA1;
            oB[nn][0] *= cB0; oB[nn][1] *= cB0;
            oB[nn][2] *= cB1; oB[nn][3] *= cB1;
        }
        uA0 += __shfl_xor_sync(0xffffffffu, uA0, 1);
        uA0 += __shfl_xor_sync(0xffffffffu, uA0, 2);
        uA1 += __shfl_xor_sync(0xffffffffu, uA1, 1);
        uA1 += __shfl_xor_sync(0xffffffffu, uA1, 2);
        uB0 += __shfl_xor_sync(0xffffffffu, uB0, 1);
        uB0 += __shfl_xor_sync(0xffffffffu, uB0, 2);
        uB1 += __shfl_xor_sync(0xffffffffu, uB1, 1);
        uB1 += __shfl_xor_sync(0xffffffffu, uB1, 2);
        lA0 += uA0; lA1 += uA1; lB0 += uB0; lB1 += uB1;

        // ---- PV in two key-halves through the per-warp P overlay (K region)
        float* wP = sm + OFF_K + wid * 1056;
#pragma unroll
        for (int h = 0; h < 2; h++) {
#pragma unroll
            for (int kkl = 0; kkl < 4; kkl++) {
                int nn = 4 * h + kkl;
#pragma unroll
                for (int ci = 0; ci < 4; ci++) {
                    int cc   = 2 * c4 + (ci & 1);
                    int slot = ((cc >= 4) ? 2 : 0) + ((ci >= 2) ? 1 : 0);
                    int lamp = gg * 4 + (cc & 3);
                    wP[kkl * 256 + lamp * 4 + slot]       = sA[nn][ci];
                    wP[kkl * 256 + 128 + lamp * 4 + slot] = sB[nn][ci];
                }
            }
            __syncwarp();
#pragma unroll
            for (int kkl = 0; kkl < 4; kkl++) {
                float4 pA = *(const float4*)&wP[kkl * 256 + lane * 4];
                float4 pB = *(const float4*)&wP[kkl * 256 + 128 + lane * 4];
                int kk = 4 * h + kkl;
#pragma unroll
                for (int w = 0; w < 4; w++) {
                    float4 vr = *(const float4*)&sm[OFF_V + kk * 528 + w * 132 + lane * 4];
                    mma_tf32(oA[2 * w],     pA.x, pA.y, pA.z, pA.w, vr.x, vr.y);
                    mma_tf32(oA[2 * w + 1], pA.x, pA.y, pA.z, pA.w, vr.z, vr.w);
                    mma_tf32(oB[2 * w],     pB.x, pB.y, pB.z, pB.w, vr.x, vr.y);
                    mma_tf32(oB[2 * w + 1], pB.x, pB.y, pB.z, pB.w, vr.z, vr.w);
                }
            }
            __syncwarp();   // half h reads done before half h+1 overwrites wP
        }
        __syncthreads();    // P region free before next tile's K staging
    }

    // ---- write partials (unnormalized O + per-row m,l)
    const int gA0 = b * SS + rA0, gA1 = b * SS + rA1;
    const int gB0 = b * SS + rB0, gB1 = b * SS + rB1;
#pragma unroll
    for (int nn = 0; nn < 8; nn++) {
        int col = nn * 8 + 2 * c4;
        *(float2*)&po[(size_t)gA0 * DHH + col] = make_float2(oA[nn][0], oA[nn][1]);
        *(float2*)&po[(size_t)gA1 * DHH + col] = make_float2(oA[nn][2], oA[nn][3]);
        *(float2*)&po[(size_t)gB0 * DHH + col] = make_float2(oB[nn][0], oB[nn][1]);
        *(float2*)&po[(size_t)gB1 * DHH + col] = make_float2(oB[nn][2], oB[nn][3]);
    }
    if (c4 == 0) {
        pml[(size_t)gA0 * 2 + 0] = mA0; pml[(size_t)gA0 * 2 + 1] = lA0;
        pml[(size_t)gA1 * 2 + 0] = mA1; pml[(size_t)gA1 * 2 + 1] = lA1;
        pml[(size_t)gB0 * 2 + 0] = mB0; pml[(size_t)gB0 * 2 + 1] = lB0;
        pml[(size_t)gB1 * 2 + 0] = mB1; pml[(size_t)gB1 * 2 + 1] = lB1;
    }
}

__global__ __launch_bounds__(256)
void fa_combine_kernel(float* __restrict__ O) {
    const int gid  = blockIdx.x * 256 + threadIdx.x;
    const int part = gid & 3;
    const int row  = gid >> 2;

    float mv[SPLITS], lv[SPLITS];
#pragma unroll
    for (int s = 0; s < SPLITS; s++) {
        mv[s] = g_ml[((size_t)s * NROWS + row) * 2 + 0];
        lv[s] = g_ml[((size_t)s * NROWS + row) * 2 + 1];
    }
    float M = fmaxf(fmaxf(mv[0], mv[1]), fmaxf(mv[2], mv[3]));
    float w[SPLITS], L = 0.f;
#pragma unroll
    for (int s = 0; s < SPLITS; s++) {
        w[s] = ex2a(mv[s] - M);
        L += w[s] * lv[s];
    }
    const float inv = 1.f / L;

    float4 acc[4];
#pragma unroll
    for (int i = 0; i < 4; i++) acc[i] = make_float4(0.f, 0.f, 0.f, 0.f);
#pragma unroll
    for (int s = 0; s < SPLITS; s++) {
        const float4* p = (const float4*)(
            g_pO + ((size_t)s * NROWS + row) * DHH + part * 16);
        float ws = w[s];
#pragma unroll
        for (int i = 0; i < 4; i++) {
            float4 v = p[i];
            acc[i].x = fmaf(ws, v.x, acc[i].x);
            acc[i].y = fmaf(ws, v.y, acc[i].y);
            acc[i].z = fmaf(ws, v.z, acc[i].z);
            acc[i].w = fmaf(ws, v.w, acc[i].w);
        }
    }
    float4* out = (float4*)(O + (size_t)row * DHH + part * 16);
#pragma unroll
    for (int i = 0; i < 4; i++) {
        float4 v = acc[i];
        v.x *= inv; v.y *= inv; v.z *= inv; v.w *= inv;
        out[i] = v;
    }
}

extern "C" void kernel_launch(void* const* d_in, const int* in_sizes, int n_in,
                              void* d_out, int out_size) {
    const float* Q = (const float*)d_in[0];
    const float* K = (const float*)d_in[1];
    const float* V = (const float*)d_in[2];
    float* O = (float*)d_out;

    cudaFuncSetAttribute(fa_mma_split,
                         cudaFuncAttributeMaxDynamicSharedMemorySize, SMEM_BYTES);
    const int grid = SPLITS * BB * (SS / BMM);   // 512 CTAs
    fa_mma_split<<<grid, NTHREADS, SMEM_BYTES>>>(Q, K, V);
    fa_combine_kernel<<<NROWS * 4 / 256, 256>>>(O);
}